// round 2
// baseline (speedup 1.0000x reference)
#include <cuda_runtime.h>
#include <cuda_fp16.h>
#include <math.h>

#define T_STEPS 1024
#define NMC     32768
#define NCTA    128
#define TPB     256

// ---- scratch (__device__ globals: no allocation allowed) -------------------
__device__ float g_c1[2 * T_STEPS * 64];   // 0.5-scaled layer-1 per-step consts
__device__ float g_mu[T_STEPS];
__device__ float g_w05[2 * 64];            // 0.5 * W1[z-row][j]
__device__ float g_part[NCTA];

// ---------------------------------------------------------------------------
// Prep: per-step layer-1 constants (pre-scaled by 0.5 for the tanh-silu) + mu
// ---------------------------------------------------------------------------
__global__ void prep_kernel(const float* __restrict__ X_seq,
                            const float* __restrict__ a,
                            const float* __restrict__ b0p,
                            const float* __restrict__ b1p,
                            const float* __restrict__ b2p,
                            const float* __restrict__ Sp,
                            const float* __restrict__ dW1,
                            const float* __restrict__ db1,
                            const float* __restrict__ gW1,
                            const float* __restrict__ gb1,
                            const int*   __restrict__ i0p)
{
    int t = blockIdx.x;            // 0..1023
    int j = threadIdx.x;           // 0..127 (two nets x 64)
    int i0 = *i0p;
    float tk = (float)(i0 + t);
    const float* x = X_seq + (size_t)(i0 + t) * 3;
    float x0 = x[0], x1 = x[1], x2 = x[2];

    int net = j >> 6, jj = j & 63;
    const float* W1 = net ? gW1 : dW1;   // [5][64] row-major; row0 = z coeff
    const float* B1 = net ? gb1 : db1;
    float v = B1[jj] + x0 * W1[64 + jj] + x1 * W1[128 + jj]
                     + x2 * W1[192 + jj] + tk * W1[256 + jj];
    g_c1[(net * T_STEPS + t) * 64 + jj] = 0.5f * v;
    if (t == 0) g_w05[net * 64 + jj] = 0.5f * W1[jj];

    if (j == 0) {
        float w = 6.283185307179586f * tk / (*Sp);
        g_mu[t] = x0 * a[0] + x1 * a[1] + x2 * a[2]
                + (*b0p) + (*b1p) * sinf(w) + (*b2p) * cosf(w);
    }
}

// ---------------------------------------------------------------------------
// helpers
// ---------------------------------------------------------------------------
// silu(2m) packed: input m = x/2 (pre-scaled); h = m*(1+tanh(m)) = silu(x)
__device__ __forceinline__ unsigned silu2(float m0, float m1) {
    __half2 m = __floats2half2_rn(m0, m1);
    unsigned mi = *reinterpret_cast<unsigned*>(&m), ti;
    asm("tanh.approx.f16x2 %0, %1;\n" : "=r"(ti) : "r"(mi));
    __half2 tt = *reinterpret_cast<__half2*>(&ti);
    __half2 h = __hfma2(m, tt, m);
    return *reinterpret_cast<unsigned*>(&h);
}

__device__ __forceinline__ void mma16816(float& c0, float& c1, float& c2, float& c3,
                                         unsigned a0, unsigned a1, unsigned a2, unsigned a3,
                                         unsigned b0, unsigned b1)
{
    asm volatile(
        "mma.sync.aligned.m16n8k16.row.col.f32.f16.f16.f32 "
        "{%0,%1,%2,%3}, {%4,%5,%6,%7}, {%8,%9}, {%0,%1,%2,%3};\n"
        : "+f"(c0), "+f"(c1), "+f"(c2), "+f"(c3)
        : "r"(a0), "r"(a1), "r"(a2), "r"(a3), "r"(b0), "r"(b1));
}

// ---------------------------------------------------------------------------
// Main: 128 CTAs x 256 paths, full 1024-step scan in-kernel
// ---------------------------------------------------------------------------
__global__ void __launch_bounds__(TPB, 1) main_kernel(
    const float* __restrict__ y_seq,
    const float* __restrict__ kappap,
    const float* __restrict__ dW2, const float* __restrict__ db2,
    const float* __restrict__ dW3, const float* __restrict__ db3,
    const float* __restrict__ gW2, const float* __restrict__ gb2,
    const float* __restrict__ gW3, const float* __restrict__ gb3,
    const float* __restrict__ xi,
    const int*   __restrict__ i0p)
{
    // W2^T staged in SMEM as b-fragments: Bs[net][n*20 + kt*4 + tg] (uint2)
    //   .x = {W2[16kt+2tg][n],   W2[16kt+2tg+1][n]}
    //   .y = {W2[16kt+8+2tg][n], W2[16kt+8+2tg+1][n]}
    // row stride 20 uint2 = 160B -> bank-pair index (4g+tg) mod 16: conflict-free
    __shared__ uint2 Bs[2][64 * 20];
    __shared__ float red[8];

    int tid  = threadIdx.x;
    int lane = tid & 31, warp = tid >> 5;
    int g = lane >> 2, tg = lane & 3;

    for (int net = 0; net < 2; net++) {
        const float* W2 = net ? gW2 : dW2;       // [k][n] row-major
        for (int e = tid; e < 64 * 16; e += TPB) {
            int n = e >> 4, sub = e & 15, kt = sub >> 2, tq = sub & 3;
            int k0 = kt * 16 + 2 * tq;
            __half2 lo = __floats2half2_rn(W2[k0 * 64 + n],       W2[(k0 + 1) * 64 + n]);
            __half2 hi = __floats2half2_rn(W2[(k0 + 8) * 64 + n], W2[(k0 + 9) * 64 + n]);
            uint2 v;
            v.x = *reinterpret_cast<unsigned*>(&lo);
            v.y = *reinterpret_cast<unsigned*>(&hi);
            Bs[net][n * 20 + kt * 4 + tq] = v;
        }
    }
    __syncthreads();

    int   i0    = *i0p;
    float kappa = *kappap;

    // layer-1 z-weights (0.5-scaled), per-lane columns
    float2 wf[2][4][2];
#pragma unroll
    for (int net = 0; net < 2; net++)
#pragma unroll
        for (int kt = 0; kt < 4; kt++) {
            int c0 = kt * 16 + 2 * tg;
            wf[net][kt][0] = __ldg((const float2*)(g_w05 + net * 64 + c0));
            wf[net][kt][1] = __ldg((const float2*)(g_w05 + net * 64 + c0 + 8));
        }

    // 0.5*b2 at this lane's output columns
    float2 hb2[2][8];
#pragma unroll
    for (int nt = 0; nt < 8; nt++) {
        int c = nt * 8 + 2 * tg;
        hb2[0][nt] = make_float2(0.5f * db2[c], 0.5f * db2[c + 1]);
        hb2[1][nt] = make_float2(0.5f * gb2[c], 0.5f * gb2[c + 1]);
    }

    // layer-3 weights as one-hot-column B fragments (col 0 <=> g==0 lanes)
    unsigned bw3[2][4][2];
#pragma unroll
    for (int net = 0; net < 2; net++) {
        const float* W3 = net ? gW3 : dW3;       // [64][1]
#pragma unroll
        for (int kt = 0; kt < 4; kt++) {
            if (g == 0) {
                int k0 = kt * 16 + 2 * tg;
                __half2 l = __floats2half2_rn(W3[k0],     W3[k0 + 1]);
                __half2 h = __floats2half2_rn(W3[k0 + 8], W3[k0 + 9]);
                bw3[net][kt][0] = *reinterpret_cast<unsigned*>(&l);
                bw3[net][kt][1] = *reinterpret_cast<unsigned*>(&h);
            } else {
                bw3[net][kt][0] = 0u; bw3[net][kt][1] = 0u;
            }
        }
    }
    float b3[2] = { db3[0], gb3[0] };

    // initial state (same for all paths)
    float y0 = fminf(fmaxf(y_seq[i0 - 1], 1e-4f), 1.0f - 1e-4f);
    float z  = logf(y0 / (1.0f - y0));

    // this lane owns path row (tg*8 + g) within its warp's 32 paths
    int pglob = blockIdx.x * 256 + warp * 32 + tg * 8 + g;
    const float* yobs = y_seq + i0;
    float ssum = 0.0f;

    for (int t = 0; t < T_STEPS; t++) {
        // gather the quad's 4 z values: z4[j] = z of row j*8+g (owner lane base+j)
        int base = lane & ~3;
        float z4[4];
#pragma unroll
        for (int j = 0; j < 4; j++) z4[j] = __shfl_sync(0xffffffffu, z, base + j);

        float xik = __ldg(xi + (size_t)t * NMC + pglob);
        float mu  = g_mu[t];
        float fg[2];

#pragma unroll
        for (int net = 0; net < 2; net++) {
            const float* c1t = g_c1 + (size_t)(net * T_STEPS + t) * 64;

            // ---- layer-1: build h1 directly as A fragments (f16) ----
            unsigned A[2][4][4];   // [mt][kt][reg]
#pragma unroll
            for (int kt = 0; kt < 4; kt++) {
                int c0 = kt * 16 + 2 * tg;
                float2 clo = __ldg((const float2*)(c1t + c0));
                float2 chi = __ldg((const float2*)(c1t + c0 + 8));
                float2 wlo = wf[net][kt][0], whi = wf[net][kt][1];
#pragma unroll
                for (int mt = 0; mt < 2; mt++) {
                    float za = z4[2 * mt], zb = z4[2 * mt + 1];
                    A[mt][kt][0] = silu2(fmaf(za, wlo.x, clo.x), fmaf(za, wlo.y, clo.y));
                    A[mt][kt][1] = silu2(fmaf(zb, wlo.x, clo.x), fmaf(zb, wlo.y, clo.y));
                    A[mt][kt][2] = silu2(fmaf(za, whi.x, chi.x), fmaf(za, whi.y, chi.y));
                    A[mt][kt][3] = silu2(fmaf(zb, whi.x, chi.x), fmaf(zb, whi.y, chi.y));
                }
            }

            // layer-3 accumulators, bias folded in (col 0 lives on tg==0 lanes)
            float d[2][4];
#pragma unroll
            for (int mt = 0; mt < 2; mt++) {
                d[mt][0] = (tg == 0) ? b3[net] : 0.0f; d[mt][1] = 0.0f;
                d[mt][2] = (tg == 0) ? b3[net] : 0.0f; d[mt][3] = 0.0f;
            }

            // ---- layer-2 GEMM + fused layer-3 MMA, n-tiles in pairs ----
#pragma unroll
            for (int ktp = 0; ktp < 4; ktp++) {
                float acc[2][2][4];
#pragma unroll
                for (int mt = 0; mt < 2; mt++)
#pragma unroll
                    for (int ntl = 0; ntl < 2; ntl++)
#pragma unroll
                        for (int c = 0; c < 4; c++) acc[mt][ntl][c] = 0.0f;

#pragma unroll
                for (int kt = 0; kt < 4; kt++) {
#pragma unroll
                    for (int ntl = 0; ntl < 2; ntl++) {
                        int n = (2 * ktp + ntl) * 8 + g;
                        uint2 b = Bs[net][n * 20 + kt * 4 + tg];
#pragma unroll
                        for (int mt = 0; mt < 2; mt++)
                            mma16816(acc[mt][ntl][0], acc[mt][ntl][1],
                                     acc[mt][ntl][2], acc[mt][ntl][3],
                                     A[mt][kt][0], A[mt][kt][1],
                                     A[mt][kt][2], A[mt][kt][3], b.x, b.y);
                    }
                }
                // epilogue: h2 = silu(acc+b2) packed as A-frag, MMA vs w3
                float2 h0 = hb2[net][2 * ktp], h1 = hb2[net][2 * ktp + 1];
#pragma unroll
                for (int mt = 0; mt < 2; mt++) {
                    unsigned e0 = silu2(fmaf(0.5f, acc[mt][0][0], h0.x),
                                        fmaf(0.5f, acc[mt][0][1], h0.y));
                    unsigned e1 = silu2(fmaf(0.5f, acc[mt][0][2], h0.x),
                                        fmaf(0.5f, acc[mt][0][3], h0.y));
                    unsigned e2 = silu2(fmaf(0.5f, acc[mt][1][0], h1.x),
                                        fmaf(0.5f, acc[mt][1][1], h1.y));
                    unsigned e3 = silu2(fmaf(0.5f, acc[mt][1][2], h1.x),
                                        fmaf(0.5f, acc[mt][1][3], h1.y));
                    mma16816(d[mt][0], d[mt][1], d[mt][2], d[mt][3],
                             e0, e1, e2, e3, bw3[net][ktp][0], bw3[net][ktp][1]);
                }
            }

            // rows {g, g+8, 16+g, 24+g} live on the quad's tg==0 lane
            float v0 = __shfl_sync(0xffffffffu, d[0][0], base);
            float v1 = __shfl_sync(0xffffffffu, d[0][2], base);
            float v2 = __shfl_sync(0xffffffffu, d[1][0], base);
            float v3 = __shfl_sync(0xffffffffu, d[1][2], base);
            fg[net] = (tg == 0) ? v0 : (tg == 1) ? v1 : (tg == 2) ? v2 : v3;
        }

        // state update (dt = 1, sqrt_dt = 1)
        float graw = fg[1];
        float gval = fmaxf(graw, 0.0f) + log1pf(__expf(-fabsf(graw))) + 1e-6f;
        z = z + kappa * (mu - z) + fg[0] + gval * xik;

        float U  = __fdividef(1.0f, 1.0f + __expf(-z));   // fp32-accurate sigmoid
        float dy = yobs[t] - U;
        ssum = fmaf(dy, dy, ssum);
    }

    // deterministic reduction: warp -> CTA -> g_part
#pragma unroll
    for (int o = 16; o; o >>= 1) ssum += __shfl_xor_sync(0xffffffffu, ssum, o);
    if (lane == 0) red[warp] = ssum;
    __syncthreads();
    if (warp == 0) {
        float s = (lane < 8) ? red[lane] : 0.0f;
#pragma unroll
        for (int o = 4; o; o >>= 1) s += __shfl_xor_sync(0xffffffffu, s, o);
        if (lane == 0) g_part[blockIdx.x] = s;
    }
}

// ---------------------------------------------------------------------------
// Finalize: reduce 128 partials, apply 0.5/sigma^2 and log-sigma terms
// ---------------------------------------------------------------------------
__global__ void fin_kernel(const float* __restrict__ lsop, float* __restrict__ out)
{
    int tid = threadIdx.x;                 // 128 threads
    float s = g_part[tid];
#pragma unroll
    for (int o = 16; o; o >>= 1) s += __shfl_xor_sync(0xffffffffu, s, o);
    __shared__ float r[4];
    if ((tid & 31) == 0) r[tid >> 5] = s;
    __syncthreads();
    if (tid == 0) {
        float tot = r[0] + r[1] + r[2] + r[3];
        float lso = *lsop;
        float sig = expf(lso) + 1e-8f;
        out[0] = 0.5f * tot / ((float)T_STEPS * (float)NMC) / (sig * sig) + lso;
    }
}

// ---------------------------------------------------------------------------
extern "C" void kernel_launch(void* const* d_in, const int* in_sizes, int n_in,
                              void* d_out, int out_size)
{
    const float* X_seq = (const float*)d_in[0];
    const float* y_seq = (const float*)d_in[1];
    const float* kappa = (const float*)d_in[2];
    const float* a     = (const float*)d_in[3];
    const float* b0    = (const float*)d_in[4];
    const float* b1    = (const float*)d_in[5];
    const float* b2    = (const float*)d_in[6];
    const float* S     = (const float*)d_in[7];
    const float* lso   = (const float*)d_in[8];
    const float* dW1   = (const float*)d_in[9];
    const float* db1   = (const float*)d_in[10];
    const float* dW2   = (const float*)d_in[11];
    const float* db2   = (const float*)d_in[12];
    const float* dW3   = (const float*)d_in[13];
    const float* db3   = (const float*)d_in[14];
    const float* gW1   = (const float*)d_in[15];
    const float* gb1   = (const float*)d_in[16];
    const float* gW2   = (const float*)d_in[17];
    const float* gb2   = (const float*)d_in[18];
    const float* gW3   = (const float*)d_in[19];
    const float* gb3   = (const float*)d_in[20];
    const float* xi    = (const float*)d_in[21];
    const int*   i0    = (const int*)d_in[22];

    prep_kernel<<<T_STEPS, 128>>>(X_seq, a, b0, b1, b2, S, dW1, db1, gW1, gb1, i0);
    main_kernel<<<NCTA, TPB>>>(y_seq, kappa, dW2, db2, dW3, db3,
                               gW2, gb2, gW3, gb3, xi, i0);
    fin_kernel<<<1, 128>>>(lso, (float*)d_out);
}

// round 3
// speedup vs baseline: 1.1038x; 1.1038x over previous
#include <cuda_runtime.h>
#include <cuda_fp16.h>
#include <math.h>

#define T_STEPS 1024
#define NMC     32768
#define NCTA    128
#define TPB     256

// ---- scratch (__device__ globals: no allocation allowed) -------------------
__device__ __half2 g_c1h[2 * T_STEPS * 32];  // 0.5-scaled layer-1 consts, half2 col pairs
__device__ __half2 g_w05h[2 * 32];           // 0.5 * W1[z-row], half2 col pairs
__device__ float   g_mu[T_STEPS];
__device__ float   g_part[NCTA];

// ---------------------------------------------------------------------------
// Prep: per-step layer-1 constants (0.5-scaled, packed half2) + mu(t)
// ---------------------------------------------------------------------------
__global__ void prep_kernel(const float* __restrict__ X_seq,
                            const float* __restrict__ a,
                            const float* __restrict__ b0p,
                            const float* __restrict__ b1p,
                            const float* __restrict__ b2p,
                            const float* __restrict__ Sp,
                            const float* __restrict__ dW1,
                            const float* __restrict__ db1,
                            const float* __restrict__ gW1,
                            const float* __restrict__ gb1,
                            const int*   __restrict__ i0p)
{
    int t = blockIdx.x;            // 0..1023
    int j = threadIdx.x;           // 0..127
    int i0 = *i0p;
    float tk = (float)(i0 + t);
    const float* x = X_seq + (size_t)(i0 + t) * 3;
    float x0 = x[0], x1 = x[1], x2 = x[2];

    int net = j >> 6, p = j & 63;  // p = column pair index (0..31 active)
    if (p < 32) {
        const float* W1 = net ? gW1 : dW1;   // [5][64] row-major; row0 = z coeff
        const float* B1 = net ? gb1 : db1;
        int c0 = 2 * p, c1c = 2 * p + 1;
        float v0 = B1[c0] + x0 * W1[64 + c0] + x1 * W1[128 + c0]
                          + x2 * W1[192 + c0] + tk * W1[256 + c0];
        float v1 = B1[c1c] + x0 * W1[64 + c1c] + x1 * W1[128 + c1c]
                           + x2 * W1[192 + c1c] + tk * W1[256 + c1c];
        g_c1h[(net * T_STEPS + t) * 32 + p] = __floats2half2_rn(0.5f * v0, 0.5f * v1);
        if (t == 0)
            g_w05h[net * 32 + p] = __floats2half2_rn(0.5f * W1[c0], 0.5f * W1[c1c]);
    }

    if (j == 0) {
        float w = 6.283185307179586f * tk / (*Sp);
        g_mu[t] = x0 * a[0] + x1 * a[1] + x2 * a[2]
                + (*b0p) + (*b1p) * sinf(w) + (*b2p) * cosf(w);
    }
}

// ---------------------------------------------------------------------------
// helpers
// ---------------------------------------------------------------------------
// silu from pre-scaled input: given m = x/2 packed half2, return m*(1+tanh(m)) = silu(x)
__device__ __forceinline__ unsigned silu2h(__half2 m) {
    unsigned mi = *reinterpret_cast<unsigned*>(&m), ti;
    asm("tanh.approx.f16x2 %0, %1;\n" : "=r"(ti) : "r"(mi));
    __half2 tt = *reinterpret_cast<__half2*>(&ti);
    __half2 h = __hfma2(m, tt, m);
    return *reinterpret_cast<unsigned*>(&h);
}

// f32-accum MMA (layer 3)
__device__ __forceinline__ void mma16816_f(float& c0, float& c1, float& c2, float& c3,
                                           unsigned a0, unsigned a1, unsigned a2, unsigned a3,
                                           unsigned b0, unsigned b1)
{
    asm volatile(
        "mma.sync.aligned.m16n8k16.row.col.f32.f16.f16.f32 "
        "{%0,%1,%2,%3}, {%4,%5,%6,%7}, {%8,%9}, {%0,%1,%2,%3};\n"
        : "+f"(c0), "+f"(c1), "+f"(c2), "+f"(c3)
        : "r"(a0), "r"(a1), "r"(a2), "r"(a3), "r"(b0), "r"(b1));
}

// f16-accum MMA (layer 2): d0 = {row g: cols 2tg,2tg+1}, d1 = {row g+8: same}
__device__ __forceinline__ void mma16816_h(unsigned& d0, unsigned& d1,
                                           unsigned a0, unsigned a1, unsigned a2, unsigned a3,
                                           unsigned b0, unsigned b1)
{
    asm volatile(
        "mma.sync.aligned.m16n8k16.row.col.f16.f16.f16.f16 "
        "{%0,%1}, {%2,%3,%4,%5}, {%6,%7}, {%0,%1};\n"
        : "+r"(d0), "+r"(d1)
        : "r"(a0), "r"(a1), "r"(a2), "r"(a3), "r"(b0), "r"(b1));
}

// ---------------------------------------------------------------------------
// Main: 128 CTAs x 256 paths, full 1024-step scan in-kernel
// ---------------------------------------------------------------------------
__global__ void __launch_bounds__(TPB, 1) main_kernel(
    const float* __restrict__ y_seq,
    const float* __restrict__ kappap,
    const float* __restrict__ dW2, const float* __restrict__ db2,
    const float* __restrict__ dW3, const float* __restrict__ db3,
    const float* __restrict__ gW2, const float* __restrict__ gb2,
    const float* __restrict__ gW3, const float* __restrict__ gb3,
    const float* __restrict__ xi,
    const int*   __restrict__ i0p)
{
    // W2^T staged in SMEM as b-fragments: Bs[net][n*20 + kt*4 + tg] (uint2)
    // row stride 20 uint2 = 160B -> conflict-free LDS.64
    __shared__ uint2 Bs[2][64 * 20];
    __shared__ float red[8];

    int tid  = threadIdx.x;
    int lane = tid & 31, warp = tid >> 5;
    int g = lane >> 2, tg = lane & 3;

    for (int net = 0; net < 2; net++) {
        const float* W2 = net ? gW2 : dW2;       // [k][n] row-major
        for (int e = tid; e < 64 * 16; e += TPB) {
            int n = e >> 4, sub = e & 15, kt = sub >> 2, tq = sub & 3;
            int k0 = kt * 16 + 2 * tq;
            __half2 lo = __floats2half2_rn(W2[k0 * 64 + n],       W2[(k0 + 1) * 64 + n]);
            __half2 hi = __floats2half2_rn(W2[(k0 + 8) * 64 + n], W2[(k0 + 9) * 64 + n]);
            uint2 v;
            v.x = *reinterpret_cast<unsigned*>(&lo);
            v.y = *reinterpret_cast<unsigned*>(&hi);
            Bs[net][n * 20 + kt * 4 + tq] = v;
        }
    }
    __syncthreads();

    int   i0    = *i0p;
    float kappa = *kappap;

    // 0.5-scaled layer-1 z-weights (half2), per-lane column pairs
    __half2 wh[2][4][2];
#pragma unroll
    for (int net = 0; net < 2; net++)
#pragma unroll
        for (int kt = 0; kt < 4; kt++) {
            wh[net][kt][0] = __ldg(g_w05h + net * 32 + kt * 8 + tg);
            wh[net][kt][1] = __ldg(g_w05h + net * 32 + kt * 8 + tg + 4);
        }

    // 0.5*b2 at this lane's output column pairs (half2)
    __half2 hb2[2][8];
#pragma unroll
    for (int nt = 0; nt < 8; nt++) {
        int c = nt * 8 + 2 * tg;
        hb2[0][nt] = __floats2half2_rn(0.5f * db2[c], 0.5f * db2[c + 1]);
        hb2[1][nt] = __floats2half2_rn(0.5f * gb2[c], 0.5f * gb2[c + 1]);
    }

    // layer-3 weights as one-hot-column B fragments (col 0 <=> g==0 lanes)
    unsigned bw3[2][4][2];
#pragma unroll
    for (int net = 0; net < 2; net++) {
        const float* W3 = net ? gW3 : dW3;       // [64][1]
#pragma unroll
        for (int kt = 0; kt < 4; kt++) {
            if (g == 0) {
                int k0 = kt * 16 + 2 * tg;
                __half2 l = __floats2half2_rn(W3[k0],     W3[k0 + 1]);
                __half2 h = __floats2half2_rn(W3[k0 + 8], W3[k0 + 9]);
                bw3[net][kt][0] = *reinterpret_cast<unsigned*>(&l);
                bw3[net][kt][1] = *reinterpret_cast<unsigned*>(&h);
            } else {
                bw3[net][kt][0] = 0u; bw3[net][kt][1] = 0u;
            }
        }
    }
    float b3[2] = { db3[0], gb3[0] };

    // initial state (same for all paths)
    float y0 = fminf(fmaxf(y_seq[i0 - 1], 1e-4f), 1.0f - 1e-4f);
    float z  = logf(y0 / (1.0f - y0));

    // this lane owns path row (tg*8 + g) within its warp's 32 paths
    int pglob = blockIdx.x * 256 + warp * 32 + tg * 8 + g;
    const float* yobs = y_seq + i0;
    float ssum = 0.0f;
    const __half2 h05 = __floats2half2_rn(0.5f, 0.5f);

    for (int t = 0; t < T_STEPS; t++) {
        // gather the quad's 4 z values (rows g, g+8, 16+g, 24+g of this warp tile)
        int base = lane & ~3;
        __half2 zh[4];
#pragma unroll
        for (int j = 0; j < 4; j++)
            zh[j] = __half2half2(__float2half(__shfl_sync(0xffffffffu, z, base + j)));

        float xik = __ldg(xi + (size_t)t * NMC + pglob);
        float mu  = g_mu[t];
        float fg[2];

#pragma unroll
        for (int net = 0; net < 2; net++) {
            const __half2* c1t = g_c1h + (size_t)(net * T_STEPS + t) * 32;

            // ---- layer-1: h1 built directly as A fragments, all half2 ----
            unsigned A[2][4][4];   // [mt][kt][reg]
#pragma unroll
            for (int kt = 0; kt < 4; kt++) {
                __half2 clo = __ldg(c1t + kt * 8 + tg);
                __half2 chi = __ldg(c1t + kt * 8 + tg + 4);
                __half2 wlo = wh[net][kt][0], whi = wh[net][kt][1];
#pragma unroll
                for (int mt = 0; mt < 2; mt++) {
                    A[mt][kt][0] = silu2h(__hfma2(zh[2 * mt],     wlo, clo));
                    A[mt][kt][1] = silu2h(__hfma2(zh[2 * mt + 1], wlo, clo));
                    A[mt][kt][2] = silu2h(__hfma2(zh[2 * mt],     whi, chi));
                    A[mt][kt][3] = silu2h(__hfma2(zh[2 * mt + 1], whi, chi));
                }
            }

            // layer-3 accumulators, bias folded in (col 0 lives on tg==0 lanes)
            float d[2][4];
#pragma unroll
            for (int mt = 0; mt < 2; mt++) {
                d[mt][0] = (tg == 0) ? b3[net] : 0.0f; d[mt][1] = 0.0f;
                d[mt][2] = (tg == 0) ? b3[net] : 0.0f; d[mt][3] = 0.0f;
            }

            // ---- layer-2 GEMM (f16 accum) + fused layer-3 MMA ----
#pragma unroll
            for (int ktp = 0; ktp < 4; ktp++) {
                unsigned acc[2][2][2];   // [mt][ntl][reg] packed half2
#pragma unroll
                for (int mt = 0; mt < 2; mt++)
#pragma unroll
                    for (int ntl = 0; ntl < 2; ntl++)
                        acc[mt][ntl][0] = acc[mt][ntl][1] = 0u;

#pragma unroll
                for (int kt = 0; kt < 4; kt++) {
#pragma unroll
                    for (int ntl = 0; ntl < 2; ntl++) {
                        int n = (2 * ktp + ntl) * 8 + g;
                        uint2 b = Bs[net][n * 20 + kt * 4 + tg];
#pragma unroll
                        for (int mt = 0; mt < 2; mt++)
                            mma16816_h(acc[mt][ntl][0], acc[mt][ntl][1],
                                       A[mt][kt][0], A[mt][kt][1],
                                       A[mt][kt][2], A[mt][kt][3], b.x, b.y);
                    }
                }
                // epilogue: h2 = silu(acc+b2) in half2, straight into layer-3 A-frag
                __half2 bb0 = hb2[net][2 * ktp], bb1 = hb2[net][2 * ktp + 1];
#pragma unroll
                for (int mt = 0; mt < 2; mt++) {
                    __half2 a00 = *reinterpret_cast<__half2*>(&acc[mt][0][0]);
                    __half2 a01 = *reinterpret_cast<__half2*>(&acc[mt][0][1]);
                    __half2 a10 = *reinterpret_cast<__half2*>(&acc[mt][1][0]);
                    __half2 a11 = *reinterpret_cast<__half2*>(&acc[mt][1][1]);
                    unsigned e0 = silu2h(__hfma2(a00, h05, bb0));  // row g,   k lo
                    unsigned e1 = silu2h(__hfma2(a01, h05, bb0));  // row g+8, k lo
                    unsigned e2 = silu2h(__hfma2(a10, h05, bb1));  // row g,   k hi
                    unsigned e3 = silu2h(__hfma2(a11, h05, bb1));  // row g+8, k hi
                    mma16816_f(d[mt][0], d[mt][1], d[mt][2], d[mt][3],
                               e0, e1, e2, e3, bw3[net][ktp][0], bw3[net][ktp][1]);
                }
            }

            // rows {g, g+8, 16+g, 24+g} col0 live on the quad's tg==0 lane
            float v0 = __shfl_sync(0xffffffffu, d[0][0], base);
            float v1 = __shfl_sync(0xffffffffu, d[0][2], base);
            float v2 = __shfl_sync(0xffffffffu, d[1][0], base);
            float v3 = __shfl_sync(0xffffffffu, d[1][2], base);
            fg[net] = (tg == 0) ? v0 : (tg == 1) ? v1 : (tg == 2) ? v2 : v3;
        }

        // state update (dt = 1, sqrt_dt = 1)
        float graw = fg[1];
        float gval = fmaxf(graw, 0.0f) + log1pf(__expf(-fabsf(graw))) + 1e-6f;
        z = z + kappa * (mu - z) + fg[0] + gval * xik;

        float U  = __fdividef(1.0f, 1.0f + __expf(-z));   // fp32-accurate sigmoid
        float dy = yobs[t] - U;
        ssum = fmaf(dy, dy, ssum);
    }

    // deterministic reduction: warp -> CTA -> g_part
#pragma unroll
    for (int o = 16; o; o >>= 1) ssum += __shfl_xor_sync(0xffffffffu, ssum, o);
    if (lane == 0) red[warp] = ssum;
    __syncthreads();
    if (warp == 0) {
        float s = (lane < 8) ? red[lane] : 0.0f;
#pragma unroll
        for (int o = 4; o; o >>= 1) s += __shfl_xor_sync(0xffffffffu, s, o);
        if (lane == 0) g_part[blockIdx.x] = s;
    }
}

// ---------------------------------------------------------------------------
// Finalize: reduce 128 partials, apply 0.5/sigma^2 and log-sigma terms
// ---------------------------------------------------------------------------
__global__ void fin_kernel(const float* __restrict__ lsop, float* __restrict__ out)
{
    int tid = threadIdx.x;                 // 128 threads
    float s = g_part[tid];
#pragma unroll
    for (int o = 16; o; o >>= 1) s += __shfl_xor_sync(0xffffffffu, s, o);
    __shared__ float r[4];
    if ((tid & 31) == 0) r[tid >> 5] = s;
    __syncthreads();
    if (tid == 0) {
        float tot = r[0] + r[1] + r[2] + r[3];
        float lso = *lsop;
        float sig = expf(lso) + 1e-8f;
        out[0] = 0.5f * tot / ((float)T_STEPS * (float)NMC) / (sig * sig) + lso;
    }
}

// ---------------------------------------------------------------------------
extern "C" void kernel_launch(void* const* d_in, const int* in_sizes, int n_in,
                              void* d_out, int out_size)
{
    const float* X_seq = (const float*)d_in[0];
    const float* y_seq = (const float*)d_in[1];
    const float* kappa = (const float*)d_in[2];
    const float* a     = (const float*)d_in[3];
    const float* b0    = (const float*)d_in[4];
    const float* b1    = (const float*)d_in[5];
    const float* b2    = (const float*)d_in[6];
    const float* S     = (const float*)d_in[7];
    const float* lso   = (const float*)d_in[8];
    const float* dW1   = (const float*)d_in[9];
    const float* db1   = (const float*)d_in[10];
    const float* dW2   = (const float*)d_in[11];
    const float* db2   = (const float*)d_in[12];
    const float* dW3   = (const float*)d_in[13];
    const float* db3   = (const float*)d_in[14];
    const float* gW1   = (const float*)d_in[15];
    const float* gb1   = (const float*)d_in[16];
    const float* gW2   = (const float*)d_in[17];
    const float* gb2   = (const float*)d_in[18];
    const float* gW3   = (const float*)d_in[19];
    const float* gb3   = (const float*)d_in[20];
    const float* xi    = (const float*)d_in[21];
    const int*   i0    = (const int*)d_in[22];

    prep_kernel<<<T_STEPS, 128>>>(X_seq, a, b0, b1, b2, S, dW1, db1, gW1, gb1, i0);
    main_kernel<<<NCTA, TPB>>>(y_seq, kappa, dW2, db2, dW3, db3,
                               gW2, gb2, gW3, gb3, xi, i0);
    fin_kernel<<<1, 128>>>(lso, (float*)d_out);
}

// round 4
// speedup vs baseline: 1.4829x; 1.3434x over previous
#include <cuda_runtime.h>
#include <cuda_fp16.h>
#include <math.h>

#define T_STEPS 1024
#define NMC     32768
#define NCTA    128
#define TPB     512

// ---- scratch (__device__ globals: no allocation allowed) -------------------
// layer-1 per-step consts, 0.5-scaled, packed per (net,t,kt,tg):
//   uint2{ half2 pair(kt*8+tg), half2 pair(kt*8+tg+4) }
__device__ uint2   g_c1p[2 * T_STEPS * 16];
__device__ __half2 g_w05h[2 * 32];           // 0.5 * W1[z-row], half2 col pairs
__device__ float   g_mu[T_STEPS];
__device__ float   g_part[NCTA];

// ---------------------------------------------------------------------------
// Prep: per-step layer-1 constants (0.5-scaled, fragment-packed) + mu(t)
// ---------------------------------------------------------------------------
__global__ void prep_kernel(const float* __restrict__ X_seq,
                            const float* __restrict__ a,
                            const float* __restrict__ b0p,
                            const float* __restrict__ b1p,
                            const float* __restrict__ b2p,
                            const float* __restrict__ Sp,
                            const float* __restrict__ dW1,
                            const float* __restrict__ db1,
                            const float* __restrict__ gW1,
                            const float* __restrict__ gb1,
                            const int*   __restrict__ i0p)
{
    int t = blockIdx.x;            // 0..1023
    int j = threadIdx.x;           // 0..127
    int i0 = *i0p;
    float tk = (float)(i0 + t);
    const float* x = X_seq + (size_t)(i0 + t) * 3;
    float x0 = x[0], x1 = x[1], x2 = x[2];

    int net = j >> 6, s = j & 63;
    const float* W1 = net ? gW1 : dW1;   // [5][64] row-major; row0 = z coeff
    const float* B1 = net ? gb1 : db1;

    if (s < 16) {
        int kt = s >> 2, tg = s & 3;
        int pl = kt * 8 + tg, ph = pl + 4;       // half2 pair indices
        float v[4];
        int cols[4] = {2 * pl, 2 * pl + 1, 2 * ph, 2 * ph + 1};
#pragma unroll
        for (int q = 0; q < 4; q++) {
            int c = cols[q];
            v[q] = B1[c] + x0 * W1[64 + c] + x1 * W1[128 + c]
                         + x2 * W1[192 + c] + tk * W1[256 + c];
        }
        __half2 lo = __floats2half2_rn(0.5f * v[0], 0.5f * v[1]);
        __half2 hi = __floats2half2_rn(0.5f * v[2], 0.5f * v[3]);
        uint2 out;
        out.x = *reinterpret_cast<unsigned*>(&lo);
        out.y = *reinterpret_cast<unsigned*>(&hi);
        g_c1p[(net * T_STEPS + t) * 16 + s] = out;
    }
    if (s >= 32 && s < 64 && t == 0) {
        int p = s - 32;                           // pair index 0..31
        g_w05h[net * 32 + p] = __floats2half2_rn(0.5f * W1[2 * p],
                                                 0.5f * W1[2 * p + 1]);
    }
    if (j == 0) {
        float w = 6.283185307179586f * tk / (*Sp);
        g_mu[t] = x0 * a[0] + x1 * a[1] + x2 * a[2]
                + (*b0p) + (*b1p) * sinf(w) + (*b2p) * cosf(w);
    }
}

// ---------------------------------------------------------------------------
// helpers
// ---------------------------------------------------------------------------
// silu from pre-scaled input: given m = x/2 packed half2, return m*(1+tanh(m)) = silu(x)
__device__ __forceinline__ unsigned silu2h(__half2 m) {
    unsigned mi = *reinterpret_cast<unsigned*>(&m), ti;
    asm("tanh.approx.f16x2 %0, %1;\n" : "=r"(ti) : "r"(mi));
    __half2 tt = *reinterpret_cast<__half2*>(&ti);
    __half2 h = __hfma2(m, tt, m);
    return *reinterpret_cast<unsigned*>(&h);
}

// f32-accum MMA (layer 3)
__device__ __forceinline__ void mma16816_f(float& c0, float& c1, float& c2, float& c3,
                                           unsigned a0, unsigned a1, unsigned a2, unsigned a3,
                                           unsigned b0, unsigned b1)
{
    asm volatile(
        "mma.sync.aligned.m16n8k16.row.col.f32.f16.f16.f32 "
        "{%0,%1,%2,%3}, {%4,%5,%6,%7}, {%8,%9}, {%0,%1,%2,%3};\n"
        : "+f"(c0), "+f"(c1), "+f"(c2), "+f"(c3)
        : "r"(a0), "r"(a1), "r"(a2), "r"(a3), "r"(b0), "r"(b1));
}

// f16-accum MMA (layer 2): d0 = {row g: cols 2tg,2tg+1}, d1 = {row g+8: same}
__device__ __forceinline__ void mma16816_h(unsigned& d0, unsigned& d1,
                                           unsigned a0, unsigned a1, unsigned a2, unsigned a3,
                                           unsigned b0, unsigned b1)
{
    asm volatile(
        "mma.sync.aligned.m16n8k16.row.col.f16.f16.f16.f16 "
        "{%0,%1}, {%2,%3,%4,%5}, {%6,%7}, {%0,%1};\n"
        : "+r"(d0), "+r"(d1)
        : "r"(a0), "r"(a1), "r"(a2), "r"(a3), "r"(b0), "r"(b1));
}

// ---------------------------------------------------------------------------
// Main: 128 CTAs x 16 warps x 16 paths, full 1024-step scan in-kernel
// ---------------------------------------------------------------------------
__global__ void __launch_bounds__(TPB, 1) main_kernel(
    const float* __restrict__ y_seq,
    const float* __restrict__ kappap,
    const float* __restrict__ dW2, const float* __restrict__ db2,
    const float* __restrict__ dW3, const float* __restrict__ db3,
    const float* __restrict__ gW2, const float* __restrict__ gb2,
    const float* __restrict__ gW3, const float* __restrict__ gb3,
    const float* __restrict__ xi,
    const int*   __restrict__ i0p)
{
    // W2^T staged in SMEM as b-fragments: Bs[net][n*20 + kt*4 + tg] (uint2)
    // row stride 20 uint2 = 160B -> conflict-free LDS.64 (per 16-lane phase)
    __shared__ uint2 Bs[2][64 * 20];
    __shared__ float red[16];

    int tid  = threadIdx.x;
    int lane = tid & 31, warp = tid >> 5;
    int g = lane >> 2, tg = lane & 3;

    for (int net = 0; net < 2; net++) {
        const float* W2 = net ? gW2 : dW2;       // [k][n] row-major
        for (int e = tid; e < 64 * 16; e += TPB) {
            int n = e >> 4, sub = e & 15, kt = sub >> 2, tq = sub & 3;
            int k0 = kt * 16 + 2 * tq;
            __half2 lo = __floats2half2_rn(W2[k0 * 64 + n],       W2[(k0 + 1) * 64 + n]);
            __half2 hi = __floats2half2_rn(W2[(k0 + 8) * 64 + n], W2[(k0 + 9) * 64 + n]);
            uint2 v;
            v.x = *reinterpret_cast<unsigned*>(&lo);
            v.y = *reinterpret_cast<unsigned*>(&hi);
            Bs[net][n * 20 + kt * 4 + tq] = v;
        }
    }
    __syncthreads();

    int   i0    = *i0p;
    float kappa = *kappap;

    // 0.5-scaled layer-1 z-weights (half2), per-lane column pairs
    __half2 wh[2][4][2];
#pragma unroll
    for (int net = 0; net < 2; net++)
#pragma unroll
        for (int kt = 0; kt < 4; kt++) {
            wh[net][kt][0] = __ldg(g_w05h + net * 32 + kt * 8 + tg);
            wh[net][kt][1] = __ldg(g_w05h + net * 32 + kt * 8 + tg + 4);
        }

    // 0.5*b2 at this lane's output column pairs (half2)
    __half2 hb2[2][8];
#pragma unroll
    for (int nt = 0; nt < 8; nt++) {
        int c = nt * 8 + 2 * tg;
        hb2[0][nt] = __floats2half2_rn(0.5f * db2[c], 0.5f * db2[c + 1]);
        hb2[1][nt] = __floats2half2_rn(0.5f * gb2[c], 0.5f * gb2[c + 1]);
    }

    // layer-3 weights as one-hot-column B fragments (col 0 <=> g==0 lanes)
    unsigned bw3[2][4][2];
#pragma unroll
    for (int net = 0; net < 2; net++) {
        const float* W3 = net ? gW3 : dW3;       // [64][1]
#pragma unroll
        for (int kp = 0; kp < 4; kp++) {
            if (g == 0) {
                int k0 = kp * 16 + 2 * tg;
                __half2 l = __floats2half2_rn(W3[k0],     W3[k0 + 1]);
                __half2 h = __floats2half2_rn(W3[k0 + 8], W3[k0 + 9]);
                bw3[net][kp][0] = *reinterpret_cast<unsigned*>(&l);
                bw3[net][kp][1] = *reinterpret_cast<unsigned*>(&h);
            } else {
                bw3[net][kp][0] = 0u; bw3[net][kp][1] = 0u;
            }
        }
    }
    float b3[2] = { db3[0], gb3[0] };

    // initial state (same for all paths)
    float y0 = fminf(fmaxf(y_seq[i0 - 1], 1e-4f), 1.0f - 1e-4f);
    float z  = logf(y0 / (1.0f - y0));

    // warp owns 16 paths; lane p<16 owns path p (lanes 16-31 mirror lanes 0-15)
    int pglob = blockIdx.x * 256 + warp * 16 + (lane & 15);
    const float* yobs = y_seq + i0;
    float ssum = 0.0f;
    const __half2 h05 = __floats2half2_rn(0.5f, 0.5f);
    int src = 4 * (lane & 7);      // layer-3 result gather source lane

    for (int t = 0; t < T_STEPS; t++) {
        // broadcast z of A-tile rows g and g+8 (path p lives on lane p)
        float za = __shfl_sync(0xffffffffu, z, g);
        float zb = __shfl_sync(0xffffffffu, z, g + 8);
        __half2 zh0 = __half2half2(__float2half(za));
        __half2 zh1 = __half2half2(__float2half(zb));

        float xik = __ldg(xi + (size_t)t * NMC + pglob);
        float mu  = g_mu[t];
        float fg[2];

#pragma unroll
        for (int net = 0; net < 2; net++) {
            const uint2* c1t = g_c1p + (size_t)(net * T_STEPS + t) * 16;

            // ---- layer-1: h1 built directly as A fragments, all half2 ----
            unsigned A[4][4];   // [kt][reg]
#pragma unroll
            for (int kt = 0; kt < 4; kt++) {
                uint2 cc = __ldg(c1t + kt * 4 + tg);
                __half2 clo = *reinterpret_cast<__half2*>(&cc.x);
                __half2 chi = *reinterpret_cast<__half2*>(&cc.y);
                __half2 wlo = wh[net][kt][0], whi = wh[net][kt][1];
                A[kt][0] = silu2h(__hfma2(zh0, wlo, clo));
                A[kt][1] = silu2h(__hfma2(zh1, wlo, clo));
                A[kt][2] = silu2h(__hfma2(zh0, whi, chi));
                A[kt][3] = silu2h(__hfma2(zh1, whi, chi));
            }

            // layer-3 accumulators, bias folded in (col 0 lives on tg==0 lanes)
            float d0 = (tg == 0) ? b3[net] : 0.0f, d1 = 0.0f;
            float d2 = (tg == 0) ? b3[net] : 0.0f, d3 = 0.0f;

            // ---- layer-2 GEMM (f16 accum) + fused layer-3 MMA ----
#pragma unroll
            for (int ktp = 0; ktp < 4; ktp++) {
                unsigned acc[2][2];   // [ntl][reg] packed half2
                acc[0][0] = acc[0][1] = acc[1][0] = acc[1][1] = 0u;
#pragma unroll
                for (int kt = 0; kt < 4; kt++) {
#pragma unroll
                    for (int ntl = 0; ntl < 2; ntl++) {
                        int n = (2 * ktp + ntl) * 8 + g;
                        uint2 b = Bs[net][n * 20 + kt * 4 + tg];
                        mma16816_h(acc[ntl][0], acc[ntl][1],
                                   A[kt][0], A[kt][1], A[kt][2], A[kt][3],
                                   b.x, b.y);
                    }
                }
                // epilogue: h2 = silu(acc+b2) in half2, straight into layer-3 A-frag
                __half2 bb0 = hb2[net][2 * ktp], bb1 = hb2[net][2 * ktp + 1];
                __half2 a00 = *reinterpret_cast<__half2*>(&acc[0][0]);
                __half2 a01 = *reinterpret_cast<__half2*>(&acc[0][1]);
                __half2 a10 = *reinterpret_cast<__half2*>(&acc[1][0]);
                __half2 a11 = *reinterpret_cast<__half2*>(&acc[1][1]);
                unsigned e0 = silu2h(__hfma2(a00, h05, bb0));  // row g,   k lo
                unsigned e1 = silu2h(__hfma2(a01, h05, bb0));  // row g+8, k lo
                unsigned e2 = silu2h(__hfma2(a10, h05, bb1));  // row g,   k hi
                unsigned e3 = silu2h(__hfma2(a11, h05, bb1));  // row g+8, k hi
                mma16816_f(d0, d1, d2, d3,
                           e0, e1, e2, e3, bw3[net][ktp][0], bw3[net][ktp][1]);
            }

            // result col0: row g on (tg==0).d0, row g+8 on (tg==0).d2
            float v0 = __shfl_sync(0xffffffffu, d0, src);
            float v2 = __shfl_sync(0xffffffffu, d2, src);
            fg[net] = (lane & 8) ? v2 : v0;
        }

        // state update (dt = 1, sqrt_dt = 1)
        float graw = fg[1];
        float gval = fmaxf(graw, 0.0f) + log1pf(__expf(-fabsf(graw))) + 1e-6f;
        z = z + kappa * (mu - z) + fg[0] + gval * xik;

        float U  = __fdividef(1.0f, 1.0f + __expf(-z));   // fp32-accurate sigmoid
        float dy = yobs[t] - U;
        ssum = fmaf(dy, dy, ssum);
    }

    // lanes 16-31 are mirrors: drop their duplicate sums
    if (lane >= 16) ssum = 0.0f;

    // deterministic reduction: warp -> CTA -> g_part
#pragma unroll
    for (int o = 16; o; o >>= 1) ssum += __shfl_xor_sync(0xffffffffu, ssum, o);
    if (lane == 0) red[warp] = ssum;
    __syncthreads();
    if (warp == 0) {
        float s = (lane < 16) ? red[lane] : 0.0f;
#pragma unroll
        for (int o = 8; o; o >>= 1) s += __shfl_xor_sync(0xffffffffu, s, o);
        if (lane == 0) g_part[blockIdx.x] = s;
    }
}

// ---------------------------------------------------------------------------
// Finalize: reduce 128 partials, apply 0.5/sigma^2 and log-sigma terms
// ---------------------------------------------------------------------------
__global__ void fin_kernel(const float* __restrict__ lsop, float* __restrict__ out)
{
    int tid = threadIdx.x;                 // 128 threads
    float s = g_part[tid];
#pragma unroll
    for (int o = 16; o; o >>= 1) s += __shfl_xor_sync(0xffffffffu, s, o);
    __shared__ float r[4];
    if ((tid & 31) == 0) r[tid >> 5] = s;
    __syncthreads();
    if (tid == 0) {
        float tot = r[0] + r[1] + r[2] + r[3];
        float lso = *lsop;
        float sig = expf(lso) + 1e-8f;
        out[0] = 0.5f * tot / ((float)T_STEPS * (float)NMC) / (sig * sig) + lso;
    }
}

// ---------------------------------------------------------------------------
extern "C" void kernel_launch(void* const* d_in, const int* in_sizes, int n_in,
                              void* d_out, int out_size)
{
    const float* X_seq = (const float*)d_in[0];
    const float* y_seq = (const float*)d_in[1];
    const float* kappa = (const float*)d_in[2];
    const float* a     = (const float*)d_in[3];
    const float* b0    = (const float*)d_in[4];
    const float* b1    = (const float*)d_in[5];
    const float* b2    = (const float*)d_in[6];
    const float* S     = (const float*)d_in[7];
    const float* lso   = (const float*)d_in[8];
    const float* dW1   = (const float*)d_in[9];
    const float* db1   = (const float*)d_in[10];
    const float* dW2   = (const float*)d_in[11];
    const float* db2   = (const float*)d_in[12];
    const float* dW3   = (const float*)d_in[13];
    const float* db3   = (const float*)d_in[14];
    const float* gW1   = (const float*)d_in[15];
    const float* gb1   = (const float*)d_in[16];
    const float* gW2   = (const float*)d_in[17];
    const float* gb2   = (const float*)d_in[18];
    const float* gW3   = (const float*)d_in[19];
    const float* gb3   = (const float*)d_in[20];
    const float* xi    = (const float*)d_in[21];
    const int*   i0    = (const int*)d_in[22];

    prep_kernel<<<T_STEPS, 128>>>(X_seq, a, b0, b1, b2, S, dW1, db1, gW1, gb1, i0);
    main_kernel<<<NCTA, TPB>>>(y_seq, kappa, dW2, db2, dW3, db3,
                               gW2, gb2, gW3, gb3, xi, i0);
    fin_kernel<<<1, 128>>>(lso, (float*)d_out);
}